// round 11
// baseline (speedup 1.0000x reference)
#include <cuda_runtime.h>
#include <cuda_fp16.h>
#include <cstdint>

// Problem constants
#define BB   8
#define HH   64
#define WWD  64
#define DD   512
#define NHH  16
#define DKK  32
#define WSS  8
#define SHH  4
#define LL   4
#define MM   (BB*HH*WWD)          // 32768 tokens

// Scratch (device globals)
__device__ __half g_qkv16[(size_t)MM * 3 * DD];   // fused q|k|v, stride 1536
__device__ __half g_xn16[(size_t)MM * DD];
__device__ __half g_at16[(size_t)MM * DD];
__device__ __half g_h16 [(size_t)MM * 4 * DD];
__device__ __half g_wqkv16[(size_t)LL * DD * 3 * DD];
__device__ float  g_bqkv  [(size_t)LL * 3 * DD];
__device__ __half g_wo16 [(size_t)LL * DD * DD];
__device__ __half g_w1_16[(size_t)LL * DD * 4 * DD];
__device__ __half g_w2_16[(size_t)LL * 4 * DD * DD];

// ---------------------------------------------------------------------------
// Baseline-PTX helpers
// ---------------------------------------------------------------------------
__device__ __forceinline__ uint32_t smem_to_u32(const void* p) {
    uint32_t a;
    asm("{ .reg .u64 t; cvta.to.shared.u64 t, %1; cvt.u32.u64 %0, t; }" : "=r"(a) : "l"(p));
    return a;
}
__device__ __forceinline__ void cp_async16(uint32_t dst, const void* src) {
    asm volatile("cp.async.cg.shared.global [%0], [%1], 16;" :: "r"(dst), "l"(src));
}
#define CP_COMMIT() asm volatile("cp.async.commit_group;" ::: "memory")
template <int N> __device__ __forceinline__ void cp_wait_group() {
    asm volatile("cp.async.wait_group %0;" :: "n"(N) : "memory");
}
__device__ __forceinline__ void ldsm_x4(uint32_t* r, uint32_t addr) {
    asm volatile("ldmatrix.sync.aligned.m8n8.x4.shared.b16 {%0,%1,%2,%3}, [%4];"
        : "=r"(r[0]), "=r"(r[1]), "=r"(r[2]), "=r"(r[3]) : "r"(addr));
}
__device__ __forceinline__ void ldsm_x4_t(uint32_t* r, uint32_t addr) {
    asm volatile("ldmatrix.sync.aligned.m8n8.x4.trans.shared.b16 {%0,%1,%2,%3}, [%4];"
        : "=r"(r[0]), "=r"(r[1]), "=r"(r[2]), "=r"(r[3]) : "r"(addr));
}
__device__ __forceinline__ void mma_f16(float* c, const uint32_t* a, const uint32_t* b) {
    asm volatile(
        "mma.sync.aligned.m16n8k16.row.col.f32.f16.f16.f32 "
        "{%0,%1,%2,%3}, {%4,%5,%6,%7}, {%8,%9}, {%0,%1,%2,%3};\n"
        : "+f"(c[0]), "+f"(c[1]), "+f"(c[2]), "+f"(c[3])
        : "r"(a[0]), "r"(a[1]), "r"(a[2]), "r"(a[3]), "r"(b[0]), "r"(b[1]));
}

// ---------------------------------------------------------------------------
// fp16 tensor-core GEMM, 3-stage cp.async pipeline.
// C = A(MxK) @ B(KxN) + bias; EPI: 0=none, 1=gelu(tanh), 2=+residual(fp32)
// CTA 128x128, BK=64, 128 threads (4 warps, 64x64 warp tiles),
// register-level fragment double-buffering.
// ---------------------------------------------------------------------------
#define HAS_STRIDE 72
#define HBS_STRIDE 136
#define HAS_BUF (128 * HAS_STRIDE)        // halves per stage
#define HBS_BUF (64 * HBS_STRIDE)
#define NSTAGE  3
#define SMEM_H  ((NSTAGE * (HAS_BUF + HBS_BUF)) * 2)   // 107520 bytes

__device__ __forceinline__ float gelu_f(float x) {
    float x3 = x * x * x;
    return 0.5f * x * (1.f + tanhf(0.7978845608028654f * (x + 0.044715f * x3)));
}
__device__ __forceinline__ void store2(float* C, size_t off, float v0, float v1) {
    float2 o; o.x = v0; o.y = v1;
    *reinterpret_cast<float2*>(C + off) = o;
}
__device__ __forceinline__ void store2(__half* C, size_t off, float v0, float v1) {
    *reinterpret_cast<__half2*>(C + off) = __floats2half2_rn(v0, v1);
}

__device__ __forceinline__ void load_frags(
    uint32_t sbA, uint32_t sbB, int kk, int wm, int wn, int lrow, int lcol8,
    uint32_t af[4][4], uint32_t bf[8][2])
{
#pragma unroll
    for (int mt = 0; mt < 4; mt++) {
        int m = wm * 64 + mt * 16 + lrow;
        ldsm_x4(af[mt], sbA + (m * HAS_STRIDE + kk + lcol8) * 2);
    }
#pragma unroll
    for (int np = 0; np < 4; np++) {
        uint32_t r4[4];
        int n = wn * 64 + np * 16 + lcol8;
        ldsm_x4_t(r4, sbB + ((kk + lrow) * HBS_STRIDE + n) * 2);
        bf[2*np][0]   = r4[0]; bf[2*np][1]   = r4[1];
        bf[2*np+1][0] = r4[2]; bf[2*np+1][1] = r4[3];
    }
}

template <int EPI, typename OutT>
__global__ void __launch_bounds__(128, 2) hgemm(
    const __half* __restrict__ A, const __half* __restrict__ Bm,
    const float* __restrict__ bias, const float* __restrict__ Rv,
    OutT* __restrict__ C, int M, int N, int K)
{
    extern __shared__ __half smh[];
    uint32_t sb = smem_to_u32(smh);
    const int tid = threadIdx.x;
    const int lane = tid & 31, wid = tid >> 5;
    const int wm = wid & 1, wn = wid >> 1;
    const int g = lane >> 2, tg = lane & 3;
    const int row0 = blockIdx.y * 128, col0 = blockIdx.x * 128;
    const int lrow = lane & 15, lcol8 = (lane >> 4) * 8;

    float acc[4][8][4];
#pragma unroll
    for (int i = 0; i < 4; i++)
#pragma unroll
        for (int j = 0; j < 8; j++)
#pragma unroll
            for (int k = 0; k < 4; k++) acc[i][j][k] = 0.f;

    const int NC = K >> 6;    // BK=64 chunks
    const uint32_t bbase = sb + NSTAGE * HAS_BUF * 2;

    // precomputed per-thread load coords
    const int arow = tid >> 3, ac8 = (tid & 7) * 8;      // A: 16 rows per iter? no: tid/8 in [0,16)
    const int brow = tid >> 4, bc8 = (tid & 15) * 8;

    // ---- stage chunks 0 and 1 ----
#pragma unroll
    for (int s = 0; s < 2; s++) {
        if (s < NC) {
            int kt = s << 6;
            uint32_t ad = sb + s * HAS_BUF * 2;
            uint32_t bd = bbase + s * HBS_BUF * 2;
#pragma unroll
            for (int i = 0; i < 8; i++) {          // A: 128 rows x 8 units
                int r = arow + i * 16;
                cp_async16(ad + (r * HAS_STRIDE + ac8) * 2,
                           A + (size_t)(row0 + r) * K + kt + ac8);
            }
#pragma unroll
            for (int i = 0; i < 8; i++) {          // B: 64 rows x 16 units
                int r = brow + i * 8;
                cp_async16(bd + (r * HBS_STRIDE + bc8) * 2,
                           Bm + (size_t)(kt + r) * N + col0 + bc8);
            }
        }
        CP_COMMIT();
    }

    uint32_t af[2][4][4], bf[2][8][2];
    int st = 0;                                    // stage of chunk c

    for (int c = 0; c < NC; c++) {
        if (c + 1 < NC) cp_wait_group<1>(); else cp_wait_group<0>();
        __syncthreads();

        // issue loads for chunk c+2 (buffer (st+2)%3 is free: its last
        // reader finished before the barrier above)
        if (c + 2 < NC) {
            int kt = (c + 2) << 6;
            int s2 = st + 2 - ((st + 2 >= NSTAGE) ? NSTAGE : 0);
            uint32_t ad = sb + s2 * HAS_BUF * 2;
            uint32_t bd = bbase + s2 * HBS_BUF * 2;
#pragma unroll
            for (int i = 0; i < 8; i++) {
                int r = arow + i * 16;
                cp_async16(ad + (r * HAS_STRIDE + ac8) * 2,
                           A + (size_t)(row0 + r) * K + kt + ac8);
            }
#pragma unroll
            for (int i = 0; i < 8; i++) {
                int r = brow + i * 8;
                cp_async16(bd + (r * HBS_STRIDE + bc8) * 2,
                           Bm + (size_t)(kt + r) * N + col0 + bc8);
            }
            CP_COMMIT();
        } else {
            CP_COMMIT();   // keep group counting uniform
        }

        uint32_t sbA = sb + st * HAS_BUF * 2;
        uint32_t sbB = bbase + st * HBS_BUF * 2;

        load_frags(sbA, sbB, 0, wm, wn, lrow, lcol8, af[0], bf[0]);
#pragma unroll
        for (int j = 0; j < 4; j++) {
            if (j < 3)
                load_frags(sbA, sbB, (j + 1) * 16, wm, wn, lrow, lcol8,
                           af[(j + 1) & 1], bf[(j + 1) & 1]);
            const int cur = j & 1;
#pragma unroll
            for (int mt = 0; mt < 4; mt++)
#pragma unroll
                for (int nt = 0; nt < 8; nt++)
                    mma_f16(acc[mt][nt], af[cur][mt], bf[cur][nt]);
        }
        st = (st + 1 == NSTAGE) ? 0 : st + 1;
    }

    // ---- epilogue from registers ----
#pragma unroll
    for (int mt = 0; mt < 4; mt++) {
#pragma unroll
        for (int nt = 0; nt < 8; nt++) {
            int r = row0 + wm * 64 + mt * 16 + g;
            int cc = col0 + wn * 64 + nt * 8 + tg * 2;
            float b0 = bias[cc], b1 = bias[cc + 1];
#pragma unroll
            for (int h = 0; h < 2; h++) {
                int rr = r + h * 8;
                size_t off = (size_t)rr * N + cc;
                float v0 = acc[mt][nt][h * 2 + 0] + b0;
                float v1 = acc[mt][nt][h * 2 + 1] + b1;
                if (EPI == 1) { v0 = gelu_f(v0); v1 = gelu_f(v1); }
                if (EPI == 2) {
                    float2 rv = *reinterpret_cast<const float2*>(Rv + off);
                    v0 += rv.x; v1 += rv.y;
                }
                store2(C, off, v0, v1);
            }
        }
    }
}

// ---------------------------------------------------------------------------
// fp32 -> fp16 conversion (8 elems/thread)
// ---------------------------------------------------------------------------
struct H8 { __half2 h[4]; };
__global__ void f2h_kernel(const float* __restrict__ in, __half* __restrict__ out, int n) {
    int i = (blockIdx.x * blockDim.x + threadIdx.x) * 8;
    if (i >= n) return;
    const float4* p = reinterpret_cast<const float4*>(in + i);
    float4 a = p[0], b = p[1];
    H8 o;
    o.h[0] = __floats2half2_rn(a.x, a.y);
    o.h[1] = __floats2half2_rn(a.z, a.w);
    o.h[2] = __floats2half2_rn(b.x, b.y);
    o.h[3] = __floats2half2_rn(b.z, b.w);
    *reinterpret_cast<H8*>(out + i) = o;
}

// Pack Wq|Wkv -> Wqkv (fp16, row-major [LL][512][1536]) and bq|bkv -> bqkv
__global__ void pack_qkv(const float* __restrict__ Wq, const float* __restrict__ Wkv,
                         const float* __restrict__ bq, const float* __restrict__ bkv,
                         __half* __restrict__ Wqkv, float* __restrict__ bqkv) {
    int idx = blockIdx.x * blockDim.x + threadIdx.x;
    int total = LL * DD * 3 * DD;
    if (idx < total) {
        int j = idx % (3 * DD);
        int r = (idx / (3 * DD)) % DD;
        int l = idx / (3 * DD * DD);
        float v = (j < DD) ? Wq[((size_t)l * DD + r) * DD + j]
                           : Wkv[((size_t)l * DD + r) * 2 * DD + (j - DD)];
        Wqkv[idx] = __float2half_rn(v);
    }
    if (idx < LL * 3 * DD) {
        int j = idx % (3 * DD);
        int l = idx / (3 * DD);
        bqkv[idx] = (j < DD) ? bq[l * DD + j] : bkv[l * 2 * DD + (j - DD)];
    }
}

// ---------------------------------------------------------------------------
// LayerNorm: one warp per token, fp16 output
// ---------------------------------------------------------------------------
__global__ void ln_kernel(const float* __restrict__ x, const float* __restrict__ g,
                          const float* __restrict__ b, __half* __restrict__ out) {
    int warp = threadIdx.x >> 5, lane = threadIdx.x & 31;
    size_t row = (size_t)blockIdx.x * 8 + warp;
    const float4* xp = reinterpret_cast<const float4*>(x + row * DD);
    float4 v[4];
    float s = 0.f;
#pragma unroll
    for (int i = 0; i < 4; i++) {
        v[i] = xp[lane + i * 32];
        s += v[i].x + v[i].y + v[i].z + v[i].w;
    }
#pragma unroll
    for (int o = 16; o; o >>= 1) s += __shfl_xor_sync(0xFFFFFFFFu, s, o);
    float mean = s * (1.f / DD);
    float vs = 0.f;
#pragma unroll
    for (int i = 0; i < 4; i++) {
        float dx;
        dx = v[i].x - mean; vs += dx * dx;
        dx = v[i].y - mean; vs += dx * dx;
        dx = v[i].z - mean; vs += dx * dx;
        dx = v[i].w - mean; vs += dx * dx;
    }
#pragma unroll
    for (int o = 16; o; o >>= 1) vs += __shfl_xor_sync(0xFFFFFFFFu, vs, o);
    float rs = rsqrtf(vs * (1.f / DD) + 1e-5f);
    const float4* gp = reinterpret_cast<const float4*>(g);
    const float4* bp = reinterpret_cast<const float4*>(b);
#pragma unroll
    for (int i = 0; i < 4; i++) {
        int idx = lane + i * 32;
        float4 gg = gp[idx], bb = bp[idx];
        __half2 h0 = __floats2half2_rn((v[i].x - mean) * rs * gg.x + bb.x,
                                       (v[i].y - mean) * rs * gg.y + bb.y);
        __half2 h1 = __floats2half2_rn((v[i].z - mean) * rs * gg.z + bb.z,
                                       (v[i].w - mean) * rs * gg.w + bb.w);
        __half2 t[2] = { h0, h1 };
        *reinterpret_cast<uint2*>(out + row * DD + idx * 4) = *reinterpret_cast<uint2*>(t);
    }
}

// ---------------------------------------------------------------------------
// Fused shifted-window attention (fused qkv fp16 in, fp16 out; fp32 math)
// ---------------------------------------------------------------------------
__global__ void __launch_bounds__(64) attn_kernel(
    const __half* __restrict__ qkv,
    const float* __restrict__ table, __half* __restrict__ out)
{
    __shared__ float ks [64][DKK];
    __shared__ float vsm[64][DKK];
    __shared__ float ssc[64][65];
    __shared__ float tbl[225];
    __shared__ int   ids[64];

    int win = blockIdx.x;
    int wi = win >> 3, wj = win & 7;
    int head = blockIdx.y, b = blockIdx.z;
    int t = threadIdx.x;

    for (int i = t; i < 225; i += 64) tbl[i] = table[i * NHH + head];

    int r = t >> 3, c = t & 7;
    int hr = wi * 8 + r, wr = wj * 8 + c;
    int hs = (hr + SHH) & (HH - 1);
    int ws2 = (wr + SHH) & (WWD - 1);
    size_t base = ((size_t)(b * HH + hs) * WWD + ws2);

    int rh = (hr < HH - WSS) ? 0 : ((hr < HH - SHH) ? 1 : 2);
    int rw = (wr < WWD - WSS) ? 0 : ((wr < WWD - SHH) ? 1 : 2);
    ids[t] = rh * 3 + rw;

    const __half* qp0 = qkv + base * 3 * DD + head * DKK;
    float qr[DKK];
    {
        const uint4* qp = reinterpret_cast<const uint4*>(qp0);
#pragma unroll
        for (int i = 0; i < 4; i++) {
            uint4 u = qp[i];
            const __half2* hp = reinterpret_cast<const __half2*>(&u);
#pragma unroll
            for (int j2 = 0; j2 < 4; j2++) {
                float2 f = __half22float2(hp[j2]);
                qr[i * 8 + j2 * 2] = f.x; qr[i * 8 + j2 * 2 + 1] = f.y;
            }
        }
        const uint4* kp = reinterpret_cast<const uint4*>(qp0 + DD);
        const uint4* vp = reinterpret_cast<const uint4*>(qp0 + 2 * DD);
#pragma unroll
        for (int i = 0; i < 4; i++) {
            uint4 u = kp[i];
            const __half2* hp = reinterpret_cast<const __half2*>(&u);
#pragma unroll
            for (int j2 = 0; j2 < 4; j2++) {
                float2 f = __half22float2(hp[j2]);
                ks[t][i * 8 + j2 * 2] = f.x; ks[t][i * 8 + j2 * 2 + 1] = f.y;
            }
            u = vp[i];
#pragma unroll
            for (int j2 = 0; j2 < 4; j2++) {
                float2 f = __half22float2(hp[j2]);
                vsm[t][i * 8 + j2 * 2] = f.x; vsm[t][i * 8 + j2 * 2 + 1] = f.y;
            }
        }
    }
    __syncthreads();

    const float SCALE = 0.17677669529663687f;
    int myid = ids[t];
    float mx = -1e30f;
#pragma unroll 4
    for (int ki = 0; ki < 64; ki++) {
        float d = 0.f;
#pragma unroll
        for (int dd = 0; dd < DKK; dd++) d = fmaf(qr[dd], ks[ki][dd], d);
        int rk = ki >> 3, ck = ki & 7;
        float s = d * SCALE + tbl[(r - rk + 7) * 15 + (c - ck + 7)];
        if (ids[ki] != myid) s = -1e9f;
        ssc[t][ki] = s;
        mx = fmaxf(mx, s);
    }
    float den = 0.f;
#pragma unroll 8
    for (int ki = 0; ki < 64; ki++) {
        float e = __expf(ssc[t][ki] - mx);
        ssc[t][ki] = e;
        den += e;
    }
    float inv = 1.f / den;
    float o[DKK] = {};
#pragma unroll 4
    for (int ki = 0; ki < 64; ki++) {
        float p = ssc[t][ki] * inv;
#pragma unroll
        for (int dd = 0; dd < DKK; dd++) o[dd] = fmaf(p, vsm[ki][dd], o[dd]);
    }
    __half* op = out + base * DD + head * DKK;
#pragma unroll
    for (int i = 0; i < 8; i++) {
        __half2 t0 = __floats2half2_rn(o[i*4],   o[i*4+1]);
        __half2 t1 = __floats2half2_rn(o[i*4+2], o[i*4+3]);
        __half2 tt[2] = { t0, t1 };
        *reinterpret_cast<uint2*>(op + i * 4) = *reinterpret_cast<uint2*>(tt);
    }
}

// ---------------------------------------------------------------------------
extern "C" void kernel_launch(void* const* d_in, const int* in_sizes, int n_in,
                              void* d_out, int out_size) {
    const float* x   = (const float*)d_in[0];
    const float* Wq  = (const float*)d_in[3];
    const float* bq  = (const float*)d_in[4];
    const float* Wkv = (const float*)d_in[5];
    const float* bkv = (const float*)d_in[6];
    const float* Wo  = (const float*)d_in[7];
    const float* bo  = (const float*)d_in[8];
    const float* rt  = (const float*)d_in[9];
    const float* l1g = (const float*)d_in[10];
    const float* l1b = (const float*)d_in[11];
    const float* l2g = (const float*)d_in[12];
    const float* l2b = (const float*)d_in[13];
    const float* W1  = (const float*)d_in[14];
    const float* b1  = (const float*)d_in[15];
    const float* W2  = (const float*)d_in[16];
    const float* b2  = (const float*)d_in[17];
    float* xo = (float*)d_out;

    __half *pqkv, *pxn, *pat, *ph, *wqkv16, *wo16, *w1_16, *w2_16;
    float* bqkv;
    cudaGetSymbolAddress((void**)&pqkv,   g_qkv16);
    cudaGetSymbolAddress((void**)&pxn,    g_xn16);
    cudaGetSymbolAddress((void**)&pat,    g_at16);
    cudaGetSymbolAddress((void**)&ph,     g_h16);
    cudaGetSymbolAddress((void**)&wqkv16, g_wqkv16);
    cudaGetSymbolAddress((void**)&bqkv,   g_bqkv);
    cudaGetSymbolAddress((void**)&wo16,   g_wo16);
    cudaGetSymbolAddress((void**)&w1_16,  g_w1_16);
    cudaGetSymbolAddress((void**)&w2_16,  g_w2_16);

    cudaFuncSetAttribute(hgemm<0, __half>, cudaFuncAttributeMaxDynamicSharedMemorySize, SMEM_H);
    cudaFuncSetAttribute(hgemm<1, __half>, cudaFuncAttributeMaxDynamicSharedMemorySize, SMEM_H);
    cudaFuncSetAttribute(hgemm<2, float>,  cudaFuncAttributeMaxDynamicSharedMemorySize, SMEM_H);

    // pack + convert weights (every call: deterministic)
    {
        int tot = LL * DD * 3 * DD;
        pack_qkv<<<(tot + 255) / 256, 256>>>(Wq, Wkv, bq, bkv, wqkv16, bqkv);
        int n;
        n = LL * DD * DD;
        f2h_kernel<<<(n / 8 + 255) / 256, 256>>>(Wo, wo16, n);
        n = LL * DD * 4 * DD;
        f2h_kernel<<<(n / 8 + 255) / 256, 256>>>(W1, w1_16, n);
        n = LL * 4 * DD * DD;
        f2h_kernel<<<(n / 8 + 255) / 256, 256>>>(W2, w2_16, n);
    }

    cudaMemcpyAsync(xo, x, (size_t)MM * DD * sizeof(float),
                    cudaMemcpyDeviceToDevice, 0);

    for (int l = 0; l < LL; l++) {
        ln_kernel<<<MM / 8, 256>>>(xo, l1g + l * DD, l1b + l * DD, pxn);
        // fused qkv = xn @ Wqkv + bqkv   (N = 1536)
        hgemm<0, __half><<<dim3(3 * DD / 128, MM / 128), 128, SMEM_H>>>(
            pxn, wqkv16 + (size_t)l * DD * 3 * DD, bqkv + (size_t)l * 3 * DD,
            nullptr, pqkv, MM, 3 * DD, DD);
        attn_kernel<<<dim3(64, NHH, BB), 64>>>(pqkv, rt + (size_t)l * 225 * NHH, pat);
        hgemm<2, float><<<dim3(DD / 128, MM / 128), 128, SMEM_H>>>(
            pat, wo16 + (size_t)l * DD * DD, bo + (size_t)l * DD, xo, xo,
            MM, DD, DD);
        ln_kernel<<<MM / 8, 256>>>(xo, l2g + l * DD, l2b + l * DD, pxn);
        hgemm<1, __half><<<dim3(4 * DD / 128, MM / 128), 128, SMEM_H>>>(
            pxn, w1_16 + (size_t)l * DD * 4 * DD, b1 + (size_t)l * 4 * DD, nullptr, ph,
            MM, 4 * DD, DD);
        hgemm<2, float><<<dim3(DD / 128, MM / 128), 128, SMEM_H>>>(
            ph, w2_16 + (size_t)l * 4 * DD * DD, b2 + (size_t)l * DD, xo, xo,
            MM, DD, 4 * DD);
    }
}

// round 13
// speedup vs baseline: 1.2670x; 1.2670x over previous
#include <cuda_runtime.h>
#include <cuda_fp16.h>
#include <cstdint>

// Problem constants
#define BB   8
#define HH   64
#define WWD  64
#define DD   512
#define NHH  16
#define DKK  32
#define WSS  8
#define SHH  4
#define LL   4
#define MM   (BB*HH*WWD)          // 32768 tokens

// Scratch (device globals)
__device__ __half g_q16 [(size_t)MM * DD];
__device__ __half g_kv16[(size_t)MM * 2 * DD];
__device__ __half g_xn16[(size_t)MM * DD];
__device__ __half g_at16[(size_t)MM * DD];
__device__ __half g_h16 [(size_t)MM * 4 * DD];
__device__ __half g_wq16 [(size_t)LL * DD * DD];
__device__ __half g_wkv16[(size_t)LL * DD * 2 * DD];
__device__ __half g_wo16 [(size_t)LL * DD * DD];
__device__ __half g_w1_16[(size_t)LL * DD * 4 * DD];
__device__ __half g_w2_16[(size_t)LL * 4 * DD * DD];

// ---------------------------------------------------------------------------
// Baseline-PTX helpers
// ---------------------------------------------------------------------------
__device__ __forceinline__ uint32_t smem_to_u32(const void* p) {
    uint32_t a;
    asm("{ .reg .u64 t; cvta.to.shared.u64 t, %1; cvt.u32.u64 %0, t; }" : "=r"(a) : "l"(p));
    return a;
}
__device__ __forceinline__ void cp_async16(uint32_t dst, const void* src) {
    asm volatile("cp.async.cg.shared.global [%0], [%1], 16;" :: "r"(dst), "l"(src));
}
#define CP_COMMIT() asm volatile("cp.async.commit_group;" ::: "memory")
template <int N> __device__ __forceinline__ void cp_wait_group() {
    asm volatile("cp.async.wait_group %0;" :: "n"(N) : "memory");
}
__device__ __forceinline__ void ldsm_x4(uint32_t* r, uint32_t addr) {
    asm volatile("ldmatrix.sync.aligned.m8n8.x4.shared.b16 {%0,%1,%2,%3}, [%4];"
        : "=r"(r[0]), "=r"(r[1]), "=r"(r[2]), "=r"(r[3]) : "r"(addr));
}
__device__ __forceinline__ void ldsm_x4_t(uint32_t* r, uint32_t addr) {
    asm volatile("ldmatrix.sync.aligned.m8n8.x4.trans.shared.b16 {%0,%1,%2,%3}, [%4];"
        : "=r"(r[0]), "=r"(r[1]), "=r"(r[2]), "=r"(r[3]) : "r"(addr));
}
__device__ __forceinline__ void mma_f16(float* c, const uint32_t* a, const uint32_t* b) {
    asm volatile(
        "mma.sync.aligned.m16n8k16.row.col.f32.f16.f16.f32 "
        "{%0,%1,%2,%3}, {%4,%5,%6,%7}, {%8,%9}, {%0,%1,%2,%3};\n"
        : "+f"(c[0]), "+f"(c[1]), "+f"(c[2]), "+f"(c[3])
        : "r"(a[0]), "r"(a[1]), "r"(a[2]), "r"(a[3]), "r"(b[0]), "r"(b[1]));
}

// ---------------------------------------------------------------------------
// fp16 tensor-core GEMM (R10 config: 2-stage dbuf + register frag dbuf)
// ---------------------------------------------------------------------------
#define HAS_STRIDE 72
#define HBS_STRIDE 136
#define HAS_BUF (128 * HAS_STRIDE)
#define HBS_BUF (64 * HBS_STRIDE)
#define SMEM_H  ((2 * HAS_BUF + 2 * HBS_BUF) * 2)   // 71680 bytes

__device__ __forceinline__ float gelu_f(float x) {
    float x3 = x * x * x;
    return 0.5f * x * (1.f + tanhf(0.7978845608028654f * (x + 0.044715f * x3)));
}
__device__ __forceinline__ void store2(float* C, size_t off, float v0, float v1) {
    float2 o; o.x = v0; o.y = v1;
    *reinterpret_cast<float2*>(C + off) = o;
}
__device__ __forceinline__ void store2(__half* C, size_t off, float v0, float v1) {
    *reinterpret_cast<__half2*>(C + off) = __floats2half2_rn(v0, v1);
}

__device__ __forceinline__ void load_frags(
    uint32_t sbA, uint32_t sbB, int kk, int wm, int wn, int lrow, int lcol8,
    uint32_t af[4][4], uint32_t bf[8][2])
{
#pragma unroll
    for (int mt = 0; mt < 4; mt++) {
        int m = wm * 64 + mt * 16 + lrow;
        ldsm_x4(af[mt], sbA + (m * HAS_STRIDE + kk + lcol8) * 2);
    }
#pragma unroll
    for (int np = 0; np < 4; np++) {
        uint32_t r4[4];
        int n = wn * 64 + np * 16 + lcol8;
        ldsm_x4_t(r4, sbB + ((kk + lrow) * HBS_STRIDE + n) * 2);
        bf[2*np][0]   = r4[0]; bf[2*np][1]   = r4[1];
        bf[2*np+1][0] = r4[2]; bf[2*np+1][1] = r4[3];
    }
}

template <int EPI, typename OutT>
__global__ void __launch_bounds__(128, 2) hgemm(
    const __half* __restrict__ A, const __half* __restrict__ Bm,
    const float* __restrict__ bias, const float* __restrict__ Rv,
    OutT* __restrict__ C, int M, int N, int K)
{
    extern __shared__ __half smh[];
    uint32_t sb = smem_to_u32(smh);
    const int tid = threadIdx.x;
    const int lane = tid & 31, wid = tid >> 5;
    const int wm = wid & 1, wn = wid >> 1;
    const int g = lane >> 2, tg = lane & 3;
    const int row0 = blockIdx.y * 128, col0 = blockIdx.x * 128;
    const int lrow = lane & 15, lcol8 = (lane >> 4) * 8;

    float acc[4][8][4];
#pragma unroll
    for (int i = 0; i < 4; i++)
#pragma unroll
        for (int j = 0; j < 8; j++)
#pragma unroll
            for (int k = 0; k < 4; k++) acc[i][j][k] = 0.f;

    const int NC = K >> 6;

    {
        uint32_t ad = sb, bd = sb + 2 * HAS_BUF * 2;
#pragma unroll
        for (int i = 0; i < 8; i++) {
            int ch = i * 128 + tid;
            int r = ch >> 3, c8 = ch & 7;
            cp_async16(ad + (r * HAS_STRIDE + c8 * 8) * 2,
                       A + (size_t)(row0 + r) * K + c8 * 8);
        }
#pragma unroll
        for (int i = 0; i < 8; i++) {
            int ch = i * 128 + tid;
            int r = ch >> 4, c8 = ch & 15;
            cp_async16(bd + (r * HBS_STRIDE + c8 * 8) * 2,
                       Bm + (size_t)r * N + col0 + c8 * 8);
        }
        CP_COMMIT();
    }

    uint32_t af[2][4][4], bf[2][8][2];

    for (int c = 0; c < NC; c++) {
        if (c + 1 < NC) {
            int kt = (c + 1) << 6;
            int nb = (c + 1) & 1;
            uint32_t ad = sb + (nb ? HAS_BUF * 2 : 0);
            uint32_t bd = sb + (2 * HAS_BUF + (nb ? HBS_BUF : 0)) * 2;
#pragma unroll
            for (int i = 0; i < 8; i++) {
                int ch = i * 128 + tid;
                int r = ch >> 3, c8 = ch & 7;
                cp_async16(ad + (r * HAS_STRIDE + c8 * 8) * 2,
                           A + (size_t)(row0 + r) * K + kt + c8 * 8);
            }
#pragma unroll
            for (int i = 0; i < 8; i++) {
                int ch = i * 128 + tid;
                int r = ch >> 4, c8 = ch & 15;
                cp_async16(bd + (r * HBS_STRIDE + c8 * 8) * 2,
                           Bm + (size_t)(kt + r) * N + col0 + c8 * 8);
            }
            CP_COMMIT();
            cp_wait_group<1>();
        } else {
            cp_wait_group<0>();
        }
        __syncthreads();

        uint32_t sbA = sb + ((c & 1) ? HAS_BUF * 2 : 0);
        uint32_t sbB = sb + (2 * HAS_BUF + ((c & 1) ? HBS_BUF : 0)) * 2;

        load_frags(sbA, sbB, 0, wm, wn, lrow, lcol8, af[0], bf[0]);
#pragma unroll
        for (int j = 0; j < 4; j++) {
            if (j < 3)
                load_frags(sbA, sbB, (j + 1) * 16, wm, wn, lrow, lcol8,
                           af[(j + 1) & 1], bf[(j + 1) & 1]);
            const int cur = j & 1;
#pragma unroll
            for (int mt = 0; mt < 4; mt++)
#pragma unroll
                for (int nt = 0; nt < 8; nt++)
                    mma_f16(acc[mt][nt], af[cur][mt], bf[cur][nt]);
        }
        __syncthreads();
    }

#pragma unroll
    for (int mt = 0; mt < 4; mt++) {
#pragma unroll
        for (int nt = 0; nt < 8; nt++) {
            int r = row0 + wm * 64 + mt * 16 + g;
            int cc = col0 + wn * 64 + nt * 8 + tg * 2;
            float b0 = bias[cc], b1 = bias[cc + 1];
#pragma unroll
            for (int h = 0; h < 2; h++) {
                int rr = r + h * 8;
                size_t off = (size_t)rr * N + cc;
                float v0 = acc[mt][nt][h * 2 + 0] + b0;
                float v1 = acc[mt][nt][h * 2 + 1] + b1;
                if (EPI == 1) { v0 = gelu_f(v0); v1 = gelu_f(v1); }
                if (EPI == 2) {
                    float2 rv = *reinterpret_cast<const float2*>(Rv + off);
                    v0 += rv.x; v1 += rv.y;
                }
                store2(C, off, v0, v1);
            }
        }
    }
}

// ---------------------------------------------------------------------------
// fp32 -> fp16 conversion
// ---------------------------------------------------------------------------
struct H8 { __half2 h[4]; };
__global__ void f2h_kernel(const float* __restrict__ in, __half* __restrict__ out, int n) {
    int i = (blockIdx.x * blockDim.x + threadIdx.x) * 8;
    if (i >= n) return;
    const float4* p = reinterpret_cast<const float4*>(in + i);
    float4 a = p[0], b = p[1];
    H8 o;
    o.h[0] = __floats2half2_rn(a.x, a.y);
    o.h[1] = __floats2half2_rn(a.z, a.w);
    o.h[2] = __floats2half2_rn(b.x, b.y);
    o.h[3] = __floats2half2_rn(b.z, b.w);
    *reinterpret_cast<H8*>(out + i) = o;
}

// ---------------------------------------------------------------------------
// LayerNorm: one warp per token, fp16 output
// ---------------------------------------------------------------------------
__global__ void ln_kernel(const float* __restrict__ x, const float* __restrict__ g,
                          const float* __restrict__ b, __half* __restrict__ out) {
    int warp = threadIdx.x >> 5, lane = threadIdx.x & 31;
    size_t row = (size_t)blockIdx.x * 8 + warp;
    const float4* xp = reinterpret_cast<const float4*>(x + row * DD);
    float4 v[4];
    float s = 0.f;
#pragma unroll
    for (int i = 0; i < 4; i++) {
        v[i] = xp[lane + i * 32];
        s += v[i].x + v[i].y + v[i].z + v[i].w;
    }
#pragma unroll
    for (int o = 16; o; o >>= 1) s += __shfl_xor_sync(0xFFFFFFFFu, s, o);
    float mean = s * (1.f / DD);
    float vs = 0.f;
#pragma unroll
    for (int i = 0; i < 4; i++) {
        float dx;
        dx = v[i].x - mean; vs += dx * dx;
        dx = v[i].y - mean; vs += dx * dx;
        dx = v[i].z - mean; vs += dx * dx;
        dx = v[i].w - mean; vs += dx * dx;
    }
#pragma unroll
    for (int o = 16; o; o >>= 1) vs += __shfl_xor_sync(0xFFFFFFFFu, vs, o);
    float rs = rsqrtf(vs * (1.f / DD) + 1e-5f);
    const float4* gp = reinterpret_cast<const float4*>(g);
    const float4* bp = reinterpret_cast<const float4*>(b);
#pragma unroll
    for (int i = 0; i < 4; i++) {
        int idx = lane + i * 32;
        float4 gg = gp[idx], bb = bp[idx];
        __half2 h0 = __floats2half2_rn((v[i].x - mean) * rs * gg.x + bb.x,
                                       (v[i].y - mean) * rs * gg.y + bb.y);
        __half2 h1 = __floats2half2_rn((v[i].z - mean) * rs * gg.z + bb.z,
                                       (v[i].w - mean) * rs * gg.w + bb.w);
        __half2 t[2] = { h0, h1 };
        *reinterpret_cast<uint2*>(out + row * DD + idx * 4) = *reinterpret_cast<uint2*>(t);
    }
}

// ---------------------------------------------------------------------------
// MMA-based fused shifted-window attention.
// Block = 128 threads (4 warps), one (window, head, batch).
// Warp w owns score rows [16w, 16w+16) of the 64x64 score matrix.
// ---------------------------------------------------------------------------
#define ATS 40   // q/k/v smem row stride (halves)
#define BMS 72   // bias-mask smem row stride (halves)

__global__ void __launch_bounds__(128) attn_mma(
    const __half* __restrict__ q, const __half* __restrict__ kv,
    const float* __restrict__ table, __half* __restrict__ out)
{
    __shared__ __half qs[64 * ATS];
    __shared__ __half ks[64 * ATS];
    __shared__ __half vs[64 * ATS];
    __shared__ __half bm[64 * BMS];
    __shared__ float tbl[225];

    const int tid = threadIdx.x;
    const int lane = tid & 31, w = tid >> 5;
    const int g = lane >> 2, tg = lane & 3;
    const int win = blockIdx.x, head = blockIdx.y, b = blockIdx.z;
    const int wi = win >> 3, wj = win & 7;

    uint32_t sq = smem_to_u32(qs), sk = smem_to_u32(ks), sv = smem_to_u32(vs);

    // stage q/k/v tiles (64 tokens x 32 halves) via cp.async
#pragma unroll
    for (int i = 0; i < 2; i++) {
        int ch = i * 128 + tid;
        int t = ch >> 2, part = (ch & 3) * 8;
        int hr = wi * 8 + (t >> 3), wr = wj * 8 + (t & 7);
        int hs = (hr + SHH) & (HH - 1), ws2 = (wr + SHH) & (WWD - 1);
        size_t base = ((size_t)(b * HH + hs) * WWD + ws2);
        cp_async16(sq + (t * ATS + part) * 2, q  + base * DD     + head * DKK + part);
        cp_async16(sk + (t * ATS + part) * 2, kv + base * 2 * DD + head * DKK + part);
        cp_async16(sv + (t * ATS + part) * 2, kv + base * 2 * DD + DD + head * DKK + part);
    }
    CP_COMMIT();

    // rel-bias table -> smem
    for (int i = tid; i < 225; i += 128) tbl[i] = table[i * NHH + head];
    __syncthreads();

    // bias+mask matrix (fp16): bm[q][k] = same-region ? tbl : -30000
#pragma unroll
    for (int i = 0; i < 32; i++) {
        int idx = i * 128 + tid;
        int qq = idx >> 6, kk2 = idx & 63;
        int rq = qq >> 3, cq = qq & 7, rk = kk2 >> 3, ck = kk2 & 7;
        int hq = wi * 8 + rq, wq2 = wj * 8 + cq;
        int hk = wi * 8 + rk, wk2 = wj * 8 + ck;
        int idq = ((hq < 56) ? 0 : (hq < 60) ? 1 : 2) * 3 + ((wq2 < 56) ? 0 : (wq2 < 60) ? 1 : 2);
        int idk = ((hk < 56) ? 0 : (hk < 60) ? 1 : 2) * 3 + ((wk2 < 56) ? 0 : (wk2 < 60) ? 1 : 2);
        float v = (idq == idk) ? tbl[(rq - rk + 7) * 15 + (cq - ck + 7)] : -30000.f;
        bm[qq * BMS + kk2] = __float2half_rn(v);
    }
    cp_wait_group<0>();
    __syncthreads();

    const int q0 = w * 16;
    const int lrow = lane & 15, lcol8 = (lane >> 4) * 8;

    // ---- scores = Q @ K^T (fp32 accum) ----
    float sc[8][4];
#pragma unroll
    for (int j = 0; j < 8; j++)
#pragma unroll
        for (int k2 = 0; k2 < 4; k2++) sc[j][k2] = 0.f;

    uint32_t aq[2][4];
    ldsm_x4(aq[0], sq + ((q0 + lrow) * ATS + 0  + lcol8) * 2);
    ldsm_x4(aq[1], sq + ((q0 + lrow) * ATS + 16 + lcol8) * 2);

    // K as B-operand: non-trans ldsm on [key][dk] storage
    const int keyb = (lane & 7) + ((lane >> 4) << 3);
    const int kcb  = ((lane >> 3) & 1) << 3;
#pragma unroll
    for (int kk2 = 0; kk2 < 2; kk2++) {
#pragma unroll
        for (int np = 0; np < 4; np++) {
            uint32_t r4[4];
            ldsm_x4(r4, sk + ((np * 16 + keyb) * ATS + kk2 * 16 + kcb) * 2);
            uint32_t b0[2] = { r4[0], r4[1] }, b1[2] = { r4[2], r4[3] };
            mma_f16(sc[2 * np],     aq[kk2], b0);
            mma_f16(sc[2 * np + 1], aq[kk2], b1);
        }
    }

    // ---- softmax over rows q0+g and q0+g+8 ----
    const float SCALE = 0.17677669529663687f;
    float f[8][4];
    float mlo = -1e30f, mhi = -1e30f;
#pragma unroll
    for (int j = 0; j < 8; j++) {
        __half2 blo = *reinterpret_cast<const __half2*>(&bm[(q0 + g) * BMS + j * 8 + tg * 2]);
        __half2 bhi = *reinterpret_cast<const __half2*>(&bm[(q0 + g + 8) * BMS + j * 8 + tg * 2]);
        float2 flo = __half22float2(blo), fhi = __half22float2(bhi);
        f[j][0] = sc[j][0] * SCALE + flo.x;
        f[j][1] = sc[j][1] * SCALE + flo.y;
        f[j][2] = sc[j][2] * SCALE + fhi.x;
        f[j][3] = sc[j][3] * SCALE + fhi.y;
        mlo = fmaxf(mlo, fmaxf(f[j][0], f[j][1]));
        mhi = fmaxf(mhi, fmaxf(f[j][2], f[j][3]));
    }
    mlo = fmaxf(mlo, __shfl_xor_sync(0xFFFFFFFFu, mlo, 1));
    mlo = fmaxf(mlo, __shfl_xor_sync(0xFFFFFFFFu, mlo, 2));
    mhi = fmaxf(mhi, __shfl_xor_sync(0xFFFFFFFFu, mhi, 1));
    mhi = fmaxf(mhi, __shfl_xor_sync(0xFFFFFFFFu, mhi, 2));

    float dlo = 0.f, dhi = 0.f;
    uint32_t ph[8][2];
#pragma unroll
    for (int j = 0; j < 8; j++) {
        float p0 = __expf(f[j][0] - mlo), p1 = __expf(f[j][1] - mlo);
        float p2 = __expf(f[j][2] - mhi), p3 = __expf(f[j][3] - mhi);
        dlo += p0 + p1; dhi += p2 + p3;
        __half2 hlo = __floats2half2_rn(p0, p1);
        __half2 hhi = __floats2half2_rn(p2, p3);
        ph[j][0] = *reinterpret_cast<uint32_t*>(&hlo);
        ph[j][1] = *reinterpret_cast<uint32_t*>(&hhi);
    }
    dlo += __shfl_xor_sync(0xFFFFFFFFu, dlo, 1);
    dlo += __shfl_xor_sync(0xFFFFFFFFu, dlo, 2);
    dhi += __shfl_xor_sync(0xFFFFFFFFu, dhi, 1);
    dhi += __shfl_xor_sync(0xFFFFFFFFu, dhi, 2);
    float invl = 1.f / dlo, invh = 1.f / dhi;

    // ---- out = P @ V ----
    float av[4][4];
#pragma unroll
    for (int j = 0; j < 4; j++)
#pragma unroll
        for (int k2 = 0; k2 < 4; k2++) av[j][k2] = 0.f;

#pragma unroll
    for (int j2 = 0; j2 < 4; j2++) {
        uint32_t a[4] = { ph[2*j2][0], ph[2*j2][1], ph[2*j2+1][0], ph[2*j2+1][1] };
#pragma unroll
        for (int np = 0; np < 2; np++) {
            uint32_t r4[4];
            ldsm_x4_t(r4, sv + ((j2 * 16 + lrow) * ATS + np * 16 + lcol8) * 2);
            uint32_t b0[2] = { r4[0], r4[1] }, b1[2] = { r4[2], r4[3] };
            mma_f16(av[2 * np],     a, b0);
            mma_f16(av[2 * np + 1], a, b1);
        }
    }

    // ---- store (roll back == write at original coords) ----
    {
        int tlo = q0 + g, thi = tlo + 8;
        int hr = wi * 8 + (tlo >> 3), wr = wj * 8 + (tlo & 7);
        size_t blo = ((size_t)(b * HH + ((hr + SHH) & (HH - 1))) * WWD + ((wr + SHH) & (WWD - 1)));
        hr = wi * 8 + (thi >> 3); wr = wj * 8 + (thi & 7);
        size_t bhi = ((size_t)(b * HH + ((hr + SHH) & (HH - 1))) * WWD + ((wr + SHH) & (WWD - 1)));
        __half* olo = out + blo * DD + head * DKK;
        __half* ohi = out + bhi * DD + head * DKK;
#pragma unroll
        for (int nt = 0; nt < 4; nt++) {
            *reinterpret_cast<__half2*>(olo + nt * 8 + tg * 2) =
                __floats2half2_rn(av[nt][0] * invl, av[nt][1] * invl);
            *reinterpret_cast<__half2*>(ohi + nt * 8 + tg * 2) =
                __floats2half2_rn(av[nt][2] * invh, av[nt][3] * invh);
        }
    }
}

// ---------------------------------------------------------------------------
extern "C" void kernel_launch(void* const* d_in, const int* in_sizes, int n_in,
                              void* d_out, int out_size) {
    const float* x   = (const float*)d_in[0];
    const float* Wq  = (const float*)d_in[3];
    const float* bq  = (const float*)d_in[4];
    const float* Wkv = (const float*)d_in[5];
    const float* bkv = (const float*)d_in[6];
    const float* Wo  = (const float*)d_in[7];
    const float* bo  = (const float*)d_in[8];
    const float* rt  = (const float*)d_in[9];
    const float* l1g = (const float*)d_in[10];
    const float* l1b = (const float*)d_in[11];
    const float* l2g = (const float*)d_in[12];
    const float* l2b = (const float*)d_in[13];
    const float* W1  = (const float*)d_in[14];
    const float* b1  = (const float*)d_in[15];
    const float* W2  = (const float*)d_in[16];
    const float* b2  = (const float*)d_in[17];
    float* xo = (float*)d_out;

    __half *pq, *pkv, *pxn, *pat, *ph, *wq16, *wkv16, *wo16, *w1_16, *w2_16;
    cudaGetSymbolAddress((void**)&pq,    g_q16);
    cudaGetSymbolAddress((void**)&pkv,   g_kv16);
    cudaGetSymbolAddress((void**)&pxn,   g_xn16);
    cudaGetSymbolAddress((void**)&pat,   g_at16);
    cudaGetSymbolAddress((void**)&ph,    g_h16);
    cudaGetSymbolAddress((void**)&wq16,  g_wq16);
    cudaGetSymbolAddress((void**)&wkv16, g_wkv16);
    cudaGetSymbolAddress((void**)&wo16,  g_wo16);
    cudaGetSymbolAddress((void**)&w1_16, g_w1_16);
    cudaGetSymbolAddress((void**)&w2_16, g_w2_16);

    cudaFuncSetAttribute(hgemm<0, __half>, cudaFuncAttributeMaxDynamicSharedMemorySize, SMEM_H);
    cudaFuncSetAttribute(hgemm<1, __half>, cudaFuncAttributeMaxDynamicSharedMemorySize, SMEM_H);
    cudaFuncSetAttribute(hgemm<2, float>,  cudaFuncAttributeMaxDynamicSharedMemorySize, SMEM_H);

    {
        int n;
        n = LL * DD * DD;
        f2h_kernel<<<(n / 8 + 255) / 256, 256>>>(Wq, wq16, n);
        n = LL * DD * 2 * DD;
        f2h_kernel<<<(n / 8 + 255) / 256, 256>>>(Wkv, wkv16, n);
        n = LL * DD * DD;
        f2h_kernel<<<(n / 8 + 255) / 256, 256>>>(Wo, wo16, n);
        n = LL * DD * 4 * DD;
        f2h_kernel<<<(n / 8 + 255) / 256, 256>>>(W1, w1_16, n);
        n = LL * 4 * DD * DD;
        f2h_kernel<<<(n / 8 + 255) / 256, 256>>>(W2, w2_16, n);
    }

    cudaMemcpyAsync(xo, x, (size_t)MM * DD * sizeof(float),
                    cudaMemcpyDeviceToDevice, 0);

    for (int l = 0; l < LL; l++) {
        ln_kernel<<<MM / 8, 256>>>(xo, l1g + l * DD, l1b + l * DD, pxn);
        hgemm<0, __half><<<dim3(DD / 128, MM / 128), 128, SMEM_H>>>(
            pxn, wq16 + (size_t)l * DD * DD, bq + (size_t)l * DD, nullptr, pq,
            MM, DD, DD);
        hgemm<0, __half><<<dim3(2 * DD / 128, MM / 128), 128, SMEM_H>>>(
            pxn, wkv16 + (size_t)l * DD * 2 * DD, bkv + (size_t)l * 2 * DD, nullptr, pkv,
            MM, 2 * DD, DD);
        attn_mma<<<dim3(64, NHH, BB), 128>>>(pq, pkv, rt + (size_t)l * 225 * NHH, pat);
        hgemm<2, float><<<dim3(DD / 128, MM / 128), 128, SMEM_H>>>(
            pat, wo16 + (size_t)l * DD * DD, bo + (size_t)l * DD, xo, xo,
            MM, DD, DD);
        ln_kernel<<<MM / 8, 256>>>(xo, l2g + l * DD, l2b + l * DD, pxn);
        hgemm<1, __half><<<dim3(4 * DD / 128, MM / 128), 128, SMEM_H>>>(
            pxn, w1_16 + (size_t)l * DD * 4 * DD, b1 + (size_t)l * 4 * DD, nullptr, ph,
            MM, 4 * DD, DD);
        hgemm<2, float><<<dim3(DD / 128, MM / 128), 128, SMEM_H>>>(
            ph, w2_16 + (size_t)l * 4 * DD * DD, b2 + (size_t)l * DD, xo, xo,
            MM, DD, 4 * DD);
    }
}

// round 14
// speedup vs baseline: 1.2767x; 1.0077x over previous
#include <cuda_runtime.h>
#include <cuda_fp16.h>
#include <cstdint>

// Problem constants
#define BB   8
#define HH   64
#define WWD  64
#define DD   512
#define NHH  16
#define DKK  32
#define WSS  8
#define SHH  4
#define LL   4
#define MM   (BB*HH*WWD)          // 32768 tokens

// Scratch (device globals)
__device__ __half g_q16 [(size_t)MM * DD];
__device__ __half g_kv16[(size_t)MM * 2 * DD];
__device__ __half g_xn16[(size_t)MM * DD];
__device__ __half g_at16[(size_t)MM * DD];
__device__ __half g_h16 [(size_t)MM * 4 * DD];
__device__ __half g_wq16 [(size_t)LL * DD * DD];
__device__ __half g_wkv16[(size_t)LL * DD * 2 * DD];
__device__ __half g_wo16 [(size_t)LL * DD * DD];
__device__ __half g_w1_16[(size_t)LL * DD * 4 * DD];
__device__ __half g_w2_16[(size_t)LL * 4 * DD * DD];
__device__ __half g_bias64[(size_t)LL * NHH * 64 * 64];   // precomputed rel-bias

// ---------------------------------------------------------------------------
// Baseline-PTX helpers
// ---------------------------------------------------------------------------
__device__ __forceinline__ uint32_t smem_to_u32(const void* p) {
    uint32_t a;
    asm("{ .reg .u64 t; cvta.to.shared.u64 t, %1; cvt.u32.u64 %0, t; }" : "=r"(a) : "l"(p));
    return a;
}
__device__ __forceinline__ void cp_async16(uint32_t dst, const void* src) {
    asm volatile("cp.async.cg.shared.global [%0], [%1], 16;" :: "r"(dst), "l"(src));
}
#define CP_COMMIT() asm volatile("cp.async.commit_group;" ::: "memory")
template <int N> __device__ __forceinline__ void cp_wait_group() {
    asm volatile("cp.async.wait_group %0;" :: "n"(N) : "memory");
}
__device__ __forceinline__ void ldsm_x4(uint32_t* r, uint32_t addr) {
    asm volatile("ldmatrix.sync.aligned.m8n8.x4.shared.b16 {%0,%1,%2,%3}, [%4];"
        : "=r"(r[0]), "=r"(r[1]), "=r"(r[2]), "=r"(r[3]) : "r"(addr));
}
__device__ __forceinline__ void ldsm_x4_t(uint32_t* r, uint32_t addr) {
    asm volatile("ldmatrix.sync.aligned.m8n8.x4.trans.shared.b16 {%0,%1,%2,%3}, [%4];"
        : "=r"(r[0]), "=r"(r[1]), "=r"(r[2]), "=r"(r[3]) : "r"(addr));
}
__device__ __forceinline__ void mma_f16(float* c, const uint32_t* a, const uint32_t* b) {
    asm volatile(
        "mma.sync.aligned.m16n8k16.row.col.f32.f16.f16.f32 "
        "{%0,%1,%2,%3}, {%4,%5,%6,%7}, {%8,%9}, {%0,%1,%2,%3};\n"
        : "+f"(c[0]), "+f"(c[1]), "+f"(c[2]), "+f"(c[3])
        : "r"(a[0]), "r"(a[1]), "r"(a[2]), "r"(a[3]), "r"(b[0]), "r"(b[1]));
}

// ---------------------------------------------------------------------------
// fp16 tensor-core GEMM (R10 config: 2-stage dbuf + register frag dbuf)
// ---------------------------------------------------------------------------
#define HAS_STRIDE 72
#define HBS_STRIDE 136
#define HAS_BUF (128 * HAS_STRIDE)
#define HBS_BUF (64 * HBS_STRIDE)
#define SMEM_H  ((2 * HAS_BUF + 2 * HBS_BUF) * 2)   // 71680 bytes

__device__ __forceinline__ float gelu_f(float x) {
    float x3 = x * x * x;
    return 0.5f * x * (1.f + tanhf(0.7978845608028654f * (x + 0.044715f * x3)));
}
__device__ __forceinline__ void store2(float* C, size_t off, float v0, float v1) {
    float2 o; o.x = v0; o.y = v1;
    *reinterpret_cast<float2*>(C + off) = o;
}
__device__ __forceinline__ void store2(__half* C, size_t off, float v0, float v1) {
    *reinterpret_cast<__half2*>(C + off) = __floats2half2_rn(v0, v1);
}

__device__ __forceinline__ void load_frags(
    uint32_t sbA, uint32_t sbB, int kk, int wm, int wn, int lrow, int lcol8,
    uint32_t af[4][4], uint32_t bf[8][2])
{
#pragma unroll
    for (int mt = 0; mt < 4; mt++) {
        int m = wm * 64 + mt * 16 + lrow;
        ldsm_x4(af[mt], sbA + (m * HAS_STRIDE + kk + lcol8) * 2);
    }
#pragma unroll
    for (int np = 0; np < 4; np++) {
        uint32_t r4[4];
        int n = wn * 64 + np * 16 + lcol8;
        ldsm_x4_t(r4, sbB + ((kk + lrow) * HBS_STRIDE + n) * 2);
        bf[2*np][0]   = r4[0]; bf[2*np][1]   = r4[1];
        bf[2*np+1][0] = r4[2]; bf[2*np+1][1] = r4[3];
    }
}

template <int EPI, typename OutT>
__global__ void __launch_bounds__(128, 2) hgemm(
    const __half* __restrict__ A, const __half* __restrict__ Bm,
    const float* __restrict__ bias, const float* __restrict__ Rv,
    OutT* __restrict__ C, int M, int N, int K)
{
    extern __shared__ __half smh[];
    uint32_t sb = smem_to_u32(smh);
    const int tid = threadIdx.x;
    const int lane = tid & 31, wid = tid >> 5;
    const int wm = wid & 1, wn = wid >> 1;
    const int g = lane >> 2, tg = lane & 3;
    const int row0 = blockIdx.y * 128, col0 = blockIdx.x * 128;
    const int lrow = lane & 15, lcol8 = (lane >> 4) * 8;

    float acc[4][8][4];
#pragma unroll
    for (int i = 0; i < 4; i++)
#pragma unroll
        for (int j = 0; j < 8; j++)
#pragma unroll
            for (int k = 0; k < 4; k++) acc[i][j][k] = 0.f;

    const int NC = K >> 6;

    {
        uint32_t ad = sb, bd = sb + 2 * HAS_BUF * 2;
#pragma unroll
        for (int i = 0; i < 8; i++) {
            int ch = i * 128 + tid;
            int r = ch >> 3, c8 = ch & 7;
            cp_async16(ad + (r * HAS_STRIDE + c8 * 8) * 2,
                       A + (size_t)(row0 + r) * K + c8 * 8);
        }
#pragma unroll
        for (int i = 0; i < 8; i++) {
            int ch = i * 128 + tid;
            int r = ch >> 4, c8 = ch & 15;
            cp_async16(bd + (r * HBS_STRIDE + c8 * 8) * 2,
                       Bm + (size_t)r * N + col0 + c8 * 8);
        }
        CP_COMMIT();
    }

    uint32_t af[2][4][4], bf[2][8][2];

    for (int c = 0; c < NC; c++) {
        if (c + 1 < NC) {
            int kt = (c + 1) << 6;
            int nb = (c + 1) & 1;
            uint32_t ad = sb + (nb ? HAS_BUF * 2 : 0);
            uint32_t bd = sb + (2 * HAS_BUF + (nb ? HBS_BUF : 0)) * 2;
#pragma unroll
            for (int i = 0; i < 8; i++) {
                int ch = i * 128 + tid;
                int r = ch >> 3, c8 = ch & 7;
                cp_async16(ad + (r * HAS_STRIDE + c8 * 8) * 2,
                           A + (size_t)(row0 + r) * K + kt + c8 * 8);
            }
#pragma unroll
            for (int i = 0; i < 8; i++) {
                int ch = i * 128 + tid;
                int r = ch >> 4, c8 = ch & 15;
                cp_async16(bd + (r * HBS_STRIDE + c8 * 8) * 2,
                           Bm + (size_t)(kt + r) * N + col0 + c8 * 8);
            }
            CP_COMMIT();
            cp_wait_group<1>();
        } else {
            cp_wait_group<0>();
        }
        __syncthreads();

        uint32_t sbA = sb + ((c & 1) ? HAS_BUF * 2 : 0);
        uint32_t sbB = sb + (2 * HAS_BUF + ((c & 1) ? HBS_BUF : 0)) * 2;

        load_frags(sbA, sbB, 0, wm, wn, lrow, lcol8, af[0], bf[0]);
#pragma unroll
        for (int j = 0; j < 4; j++) {
            if (j < 3)
                load_frags(sbA, sbB, (j + 1) * 16, wm, wn, lrow, lcol8,
                           af[(j + 1) & 1], bf[(j + 1) & 1]);
            const int cur = j & 1;
#pragma unroll
            for (int mt = 0; mt < 4; mt++)
#pragma unroll
                for (int nt = 0; nt < 8; nt++)
                    mma_f16(acc[mt][nt], af[cur][mt], bf[cur][nt]);
        }
        __syncthreads();
    }

#pragma unroll
    for (int mt = 0; mt < 4; mt++) {
#pragma unroll
        for (int nt = 0; nt < 8; nt++) {
            int r = row0 + wm * 64 + mt * 16 + g;
            int cc = col0 + wn * 64 + nt * 8 + tg * 2;
            float b0 = bias[cc], b1 = bias[cc + 1];
#pragma unroll
            for (int h = 0; h < 2; h++) {
                int rr = r + h * 8;
                size_t off = (size_t)rr * N + cc;
                float v0 = acc[mt][nt][h * 2 + 0] + b0;
                float v1 = acc[mt][nt][h * 2 + 1] + b1;
                if (EPI == 1) { v0 = gelu_f(v0); v1 = gelu_f(v1); }
                if (EPI == 2) {
                    float2 rv = *reinterpret_cast<const float2*>(Rv + off);
                    v0 += rv.x; v1 += rv.y;
                }
                store2(C, off, v0, v1);
            }
        }
    }
}

// ---------------------------------------------------------------------------
// fp32 -> fp16 conversion
// ---------------------------------------------------------------------------
struct H8 { __half2 h[4]; };
__global__ void f2h_kernel(const float* __restrict__ in, __half* __restrict__ out, int n) {
    int i = (blockIdx.x * blockDim.x + threadIdx.x) * 8;
    if (i >= n) return;
    const float4* p = reinterpret_cast<const float4*>(in + i);
    float4 a = p[0], b = p[1];
    H8 o;
    o.h[0] = __floats2half2_rn(a.x, a.y);
    o.h[1] = __floats2half2_rn(a.z, a.w);
    o.h[2] = __floats2half2_rn(b.x, b.y);
    o.h[3] = __floats2half2_rn(b.z, b.w);
    *reinterpret_cast<H8*>(out + i) = o;
}

// Precompute per-(layer, head) 64x64 relative-position bias matrices (fp16)
__global__ void build_bias(const float* __restrict__ rt, __half* __restrict__ bias64) {
    int idx = blockIdx.x * blockDim.x + threadIdx.x;
    if (idx >= LL * NHH * 64 * 64) return;
    int kk = idx & 63, qq = (idx >> 6) & 63, h = (idx >> 12) & (NHH - 1), l = idx >> 16;
    int rq = qq >> 3, cq = qq & 7, rk = kk >> 3, ck = kk & 7;
    int ti = (rq - rk + 7) * 15 + (cq - ck + 7);
    bias64[idx] = __float2half_rn(rt[((size_t)l * 225 + ti) * NHH + h]);
}

// ---------------------------------------------------------------------------
// LayerNorm: one warp per token, fp16 output
// ---------------------------------------------------------------------------
__global__ void ln_kernel(const float* __restrict__ x, const float* __restrict__ g,
                          const float* __restrict__ b, __half* __restrict__ out) {
    int warp = threadIdx.x >> 5, lane = threadIdx.x & 31;
    size_t row = (size_t)blockIdx.x * 8 + warp;
    const float4* xp = reinterpret_cast<const float4*>(x + row * DD);
    float4 v[4];
    float s = 0.f;
#pragma unroll
    for (int i = 0; i < 4; i++) {
        v[i] = xp[lane + i * 32];
        s += v[i].x + v[i].y + v[i].z + v[i].w;
    }
#pragma unroll
    for (int o = 16; o; o >>= 1) s += __shfl_xor_sync(0xFFFFFFFFu, s, o);
    float mean = s * (1.f / DD);
    float vs = 0.f;
#pragma unroll
    for (int i = 0; i < 4; i++) {
        float dx;
        dx = v[i].x - mean; vs += dx * dx;
        dx = v[i].y - mean; vs += dx * dx;
        dx = v[i].z - mean; vs += dx * dx;
        dx = v[i].w - mean; vs += dx * dx;
    }
#pragma unroll
    for (int o = 16; o; o >>= 1) vs += __shfl_xor_sync(0xFFFFFFFFu, vs, o);
    float rs = rsqrtf(vs * (1.f / DD) + 1e-5f);
    const float4* gp = reinterpret_cast<const float4*>(g);
    const float4* bp = reinterpret_cast<const float4*>(b);
#pragma unroll
    for (int i = 0; i < 4; i++) {
        int idx = lane + i * 32;
        float4 gg = gp[idx], bb = bp[idx];
        __half2 h0 = __floats2half2_rn((v[i].x - mean) * rs * gg.x + bb.x,
                                       (v[i].y - mean) * rs * gg.y + bb.y);
        __half2 h1 = __floats2half2_rn((v[i].z - mean) * rs * gg.z + bb.z,
                                       (v[i].w - mean) * rs * gg.w + bb.w);
        __half2 t[2] = { h0, h1 };
        *reinterpret_cast<uint2*>(out + row * DD + idx * 4) = *reinterpret_cast<uint2*>(t);
    }
}

// ---------------------------------------------------------------------------
// MMA-based fused shifted-window attention, v2:
// bias loaded from precomputed global table; shift mask applied analytically
// in registers (edge windows only). smem: q/k/v tiles only (15 KB).
// ---------------------------------------------------------------------------
#define ATS 40   // q/k/v smem row stride (halves)

__device__ __forceinline__ int region9(int h, int wv) {
    return ((h < 56) ? 0 : (h < 60) ? 1 : 2) * 3 + ((wv < 56) ? 0 : (wv < 60) ? 1 : 2);
}

__global__ void __launch_bounds__(128) attn_mma(
    const __half* __restrict__ q, const __half* __restrict__ kv,
    const __half* __restrict__ bias64, __half* __restrict__ out)
{
    __shared__ __half qs[64 * ATS];
    __shared__ __half ks[64 * ATS];
    __shared__ __half vs[64 * ATS];

    const int tid = threadIdx.x;
    const int lane = tid & 31, w = tid >> 5;
    const int g = lane >> 2, tg = lane & 3;
    const int win = blockIdx.x, head = blockIdx.y, b = blockIdx.z;
    const int wi = win >> 3, wj = win & 7;
    const bool edge = (wi == 7) || (wj == 7);

    uint32_t sq = smem_to_u32(qs), sk = smem_to_u32(ks), sv = smem_to_u32(vs);

    // stage q/k/v tiles (64 tokens x 32 halves) via cp.async
#pragma unroll
    for (int i = 0; i < 2; i++) {
        int ch = i * 128 + tid;
        int t = ch >> 2, part = (ch & 3) * 8;
        int hr = wi * 8 + (t >> 3), wr = wj * 8 + (t & 7);
        int hs = (hr + SHH) & (HH - 1), ws2 = (wr + SHH) & (WWD - 1);
        size_t base = ((size_t)(b * HH + hs) * WWD + ws2);
        cp_async16(sq + (t * ATS + part) * 2, q  + base * DD     + head * DKK + part);
        cp_async16(sk + (t * ATS + part) * 2, kv + base * 2 * DD + head * DKK + part);
        cp_async16(sv + (t * ATS + part) * 2, kv + base * 2 * DD + DD + head * DKK + part);
    }
    CP_COMMIT();
    cp_wait_group<0>();
    __syncthreads();

    const int q0 = w * 16;
    const int lrow = lane & 15, lcol8 = (lane >> 4) * 8;

    // ---- scores = Q @ K^T (fp32 accum) ----
    float sc[8][4];
#pragma unroll
    for (int j = 0; j < 8; j++)
#pragma unroll
        for (int k2 = 0; k2 < 4; k2++) sc[j][k2] = 0.f;

    uint32_t aq[2][4];
    ldsm_x4(aq[0], sq + ((q0 + lrow) * ATS + 0  + lcol8) * 2);
    ldsm_x4(aq[1], sq + ((q0 + lrow) * ATS + 16 + lcol8) * 2);

    // K as B-operand: non-trans ldsm on [key][dk] storage
    const int keyb = (lane & 7) + ((lane >> 4) << 3);
    const int kcb  = ((lane >> 3) & 1) << 3;
#pragma unroll
    for (int kk2 = 0; kk2 < 2; kk2++) {
#pragma unroll
        for (int np = 0; np < 4; np++) {
            uint32_t r4[4];
            ldsm_x4(r4, sk + ((np * 16 + keyb) * ATS + kk2 * 16 + kcb) * 2);
            uint32_t b0[2] = { r4[0], r4[1] }, b1[2] = { r4[2], r4[3] };
            mma_f16(sc[2 * np],     aq[kk2], b0);
            mma_f16(sc[2 * np + 1], aq[kk2], b1);
        }
    }

    // ---- softmax over rows q0+g and q0+g+8 ----
    const float SCALE = 0.17677669529663687f;
    const int tlo = q0 + g, thi = tlo + 8;
    const __half2* gb2 = reinterpret_cast<const __half2*>(bias64 + head * 4096);

    int idqlo = 0, idqhi = 0;
    if (edge) {
        idqlo = region9(wi * 8 + (tlo >> 3), wj * 8 + (tlo & 7));
        idqhi = region9(wi * 8 + (thi >> 3), wj * 8 + (thi & 7));
    }

    float f[8][4];
    float mlo = -1e30f, mhi = -1e30f;
#pragma unroll
    for (int j = 0; j < 8; j++) {
        __half2 blo = gb2[tlo * 32 + j * 4 + tg];
        __half2 bhi = gb2[thi * 32 + j * 4 + tg];
        float2 flo = __half22float2(blo), fhi = __half22float2(bhi);
        f[j][0] = sc[j][0] * SCALE + flo.x;
        f[j][1] = sc[j][1] * SCALE + flo.y;
        f[j][2] = sc[j][2] * SCALE + fhi.x;
        f[j][3] = sc[j][3] * SCALE + fhi.y;
        if (edge) {
            int c0 = j * 8 + tg * 2;
            int rk = c0 >> 3, ck0 = c0 & 7;
            int idr = ((wi * 8 + rk) < 56 ? 0 : (wi * 8 + rk) < 60 ? 1 : 2) * 3;
            int wk0 = wj * 8 + ck0, wk1 = wk0 + 1;
            int idk0 = idr + (wk0 < 56 ? 0 : wk0 < 60 ? 1 : 2);
            int idk1 = idr + (wk1 < 56 ? 0 : wk1 < 60 ? 1 : 2);
            if (idk0 != idqlo) f[j][0] = -1e9f;
            if (idk1 != idqlo) f[j][1] = -1e9f;
            if (idk0 != idqhi) f[j][2] = -1e9f;
            if (idk1 != idqhi) f[j][3] = -1e9f;
        }
        mlo = fmaxf(mlo, fmaxf(f[j][0], f[j][1]));
        mhi = fmaxf(mhi, fmaxf(f[j][2], f[j][3]));
    }
    mlo = fmaxf(mlo, __shfl_xor_sync(0xFFFFFFFFu, mlo, 1));
    mlo = fmaxf(mlo, __shfl_xor_sync(0xFFFFFFFFu, mlo, 2));
    mhi = fmaxf(mhi, __shfl_xor_sync(0xFFFFFFFFu, mhi, 1));
    mhi = fmaxf(mhi, __shfl_xor_sync(0xFFFFFFFFu, mhi, 2));

    float dlo = 0.f, dhi = 0.f;
    uint32_t ph[8][2];
#pragma unroll
    for (int j = 0; j < 8; j++) {
        float p0 = __expf(f[j][0] - mlo), p1 = __expf(f[j][1] - mlo);
        float p2 = __expf(f[j][2] - mhi), p3 = __expf(f[j][3] - mhi);
        dlo += p0 + p1; dhi += p2 + p3;
        __half2 hlo = __floats2half2_rn(p0, p1);
        __half2 hhi = __floats2half2_rn(p2, p3);
        ph[j][0] = *reinterpret_cast<uint32_t*>(&hlo);
        ph[j][1] = *reinterpret_cast<uint32_t*>(&hhi);
    }
    dlo += __shfl_xor_sync(0xFFFFFFFFu, dlo, 1);
    dlo += __shfl_xor_sync(0xFFFFFFFFu, dlo, 2);
    dhi += __shfl_xor_sync(0xFFFFFFFFu, dhi, 1);
    dhi += __shfl_xor_sync(0xFFFFFFFFu, dhi, 2);
    float invl = 1.f / dlo, invh = 1.f / dhi;

    // ---- out = P @ V ----
    float av[4][4];
#pragma unroll
    for (int j = 0; j < 4; j++)
#pragma unroll
        for (int k2 = 0; k2 < 4; k2++) av[j][k2] = 0.f;

#pragma unroll
    for (int j2 = 0; j2 < 4; j2++) {
        uint32_t a[4] = { ph[2*j2][0], ph[2*j2][1], ph[2*j2+1][0], ph[2*j2+1][1] };
#pragma unroll
        for (int np = 0; np < 2; np++) {
            uint32_t r4[4];
            ldsm_x4_t(r4, sv + ((j2 * 16 + lrow) * ATS + np * 16 + lcol8) * 2);
            uint32_t b0[2] = { r4[0], r4[1] }, b1[2] = { r4[2], r4[3] };
            mma_f16(av[2 * np],     a, b0);
            mma_f16(av[2 * np + 1], a, b1);
        }
    }

    // ---- store (roll back == write at original coords) ----
    {
        int hr = wi * 8 + (tlo >> 3), wr = wj * 8 + (tlo & 7);
        size_t blo = ((size_t)(b * HH + ((hr + SHH) & (HH - 1))) * WWD + ((wr + SHH) & (WWD - 1)));
        hr = wi * 8 + (thi >> 3); wr = wj * 8 + (thi & 7);
        size_t bhi = ((size_t)(b * HH + ((hr + SHH) & (HH - 1))) * WWD + ((wr + SHH) & (WWD - 1)));
        __half* olo = out + blo * DD + head * DKK;
        __half* ohi = out + bhi * DD + head * DKK;
#pragma unroll
        for (int nt = 0; nt < 4; nt++) {
            *reinterpret_cast<__half2*>(olo + nt * 8 + tg * 2) =
                __floats2half2_rn(av[nt][0] * invl, av[nt][1] * invl);
            *reinterpret_cast<__half2*>(ohi + nt * 8 + tg * 2) =
                __floats2half2_rn(av[nt][2] * invh, av[nt][3] * invh);
        }
    }
}

// ---------------------------------------------------------------------------
extern "C" void kernel_launch(void* const* d_in, const int* in_sizes, int n_in,
                              void* d_out, int out_size) {
    const float* x   = (const float*)d_in[0];
    const float* Wq  = (const float*)d_in[3];
    const float* bq  = (const float*)d_in[4];
    const float* Wkv = (const float*)d_in[5];
    const float* bkv = (const float*)d_in[6];
    const float* Wo  = (const float*)d_in[7];
    const float* bo  = (const float*)d_in[8];
    const float* rt  = (const float*)d_in[9];
    const float* l1g = (const float*)d_in[10];
    const float* l1b = (const float*)d_in[11];
    const float* l2g = (const float*)d_in[12];
    const float* l2b = (const float*)d_in[13];
    const float* W1  = (const float*)d_in[14];
    const float* b1  = (const float*)d_in[15];
    const float* W2  = (const float*)d_in[16];
    const float* b2  = (const float*)d_in[17];
    float* xo = (float*)d_out;

    __half *pq, *pkv, *pxn, *pat, *ph, *wq16, *wkv16, *wo16, *w1_16, *w2_16, *pbias;
    cudaGetSymbolAddress((void**)&pq,    g_q16);
    cudaGetSymbolAddress((void**)&pkv,   g_kv16);
    cudaGetSymbolAddress((void**)&pxn,   g_xn16);
    cudaGetSymbolAddress((void**)&pat,   g_at16);
    cudaGetSymbolAddress((void**)&ph,    g_h16);
    cudaGetSymbolAddress((void**)&wq16,  g_wq16);
    cudaGetSymbolAddress((void**)&wkv16, g_wkv16);
    cudaGetSymbolAddress((void**)&wo16,  g_wo16);
    cudaGetSymbolAddress((void**)&w1_16, g_w1_16);
    cudaGetSymbolAddress((void**)&w2_16, g_w2_16);
    cudaGetSymbolAddress((void**)&pbias, g_bias64);

    cudaFuncSetAttribute(hgemm<0, __half>, cudaFuncAttributeMaxDynamicSharedMemorySize, SMEM_H);
    cudaFuncSetAttribute(hgemm<1, __half>, cudaFuncAttributeMaxDynamicSharedMemorySize, SMEM_H);
    cudaFuncSetAttribute(hgemm<2, float>,  cudaFuncAttributeMaxDynamicSharedMemorySize, SMEM_H);

    {
        int n;
        n = LL * DD * DD;
        f2h_kernel<<<(n / 8 + 255) / 256, 256>>>(Wq, wq16, n);
        n = LL * DD * 2 * DD;
        f2h_kernel<<<(n / 8 + 255) / 256, 256>>>(Wkv, wkv16, n);
        n = LL * DD * DD;
        f2h_kernel<<<(n / 8 + 255) / 256, 256>>>(Wo, wo16, n);
        n = LL * DD * 4 * DD;
        f2h_kernel<<<(n / 8 + 255) / 256, 256>>>(W1, w1_16, n);
        n = LL * 4 * DD * DD;
        f2h_kernel<<<(n / 8 + 255) / 256, 256>>>(W2, w2_16, n);
        build_bias<<<(LL * NHH * 64 * 64 + 255) / 256, 256>>>(rt, pbias);
    }

    cudaMemcpyAsync(xo, x, (size_t)MM * DD * sizeof(float),
                    cudaMemcpyDeviceToDevice, 0);

    for (int l = 0; l < LL; l++) {
        ln_kernel<<<MM / 8, 256>>>(xo, l1g + l * DD, l1b + l * DD, pxn);
        hgemm<0, __half><<<dim3(DD / 128, MM / 128), 128, SMEM_H>>>(
            pxn, wq16 + (size_t)l * DD * DD, bq + (size_t)l * DD, nullptr, pq,
            MM, DD, DD);
        hgemm<0, __half><<<dim3(2 * DD / 128, MM / 128), 128, SMEM_H>>>(
            pxn, wkv16 + (size_t)l * DD * 2 * DD, bkv + (size_t)l * 2 * DD, nullptr, pkv,
            MM, 2 * DD, DD);
        attn_mma<<<dim3(64, NHH, BB), 128>>>(pq, pkv, pbias + (size_t)l * NHH * 4096, pat);
        hgemm<2, float><<<dim3(DD / 128, MM / 128), 128, SMEM_H>>>(
            pat, wo16 + (size_t)l * DD * DD, bo + (size_t)l * DD, xo, xo,
            MM, DD, DD);
        ln_kernel<<<MM / 8, 256>>>(xo, l2g + l * DD, l2b + l * DD, pxn);
        hgemm<1, __half><<<dim3(4 * DD / 128, MM / 128), 128, SMEM_H>>>(
            pxn, w1_16 + (size_t)l * DD * 4 * DD, b1 + (size_t)l * 4 * DD, nullptr, ph,
            MM, 4 * DD, DD);
        hgemm<2, float><<<dim3(DD / 128, MM / 128), 128, SMEM_H>>>(
            ph, w2_16 + (size_t)l * 4 * DD * DD, b2 + (size_t)l * DD, xo, xo,
            MM, DD, 4 * DD);
    }
}